// round 1
// baseline (speedup 1.0000x reference)
#include <cuda_runtime.h>
#include <cuda_bf16.h>

// Fused Swin-window cross-attention, tf32 mma.sync path.
// C=256, H=W=384, WS=4, N=16 tokens/window, 8 heads, hd=32.
// One CTA = 4 horizontally adjacent windows (64 tokens), 256 threads.

#define LDA 260   // row stride (floats) for 64x256 activation buffers (pad 4 -> conflict-free frags)
#define LDQ 36    // row stride for per-head 64x32 Q/K/V buffers

constexpr int OFF_QIN  = 0;              // 64*260
constexpr int OFF_KVIN = 16640;          // 64*260
constexpr int OFF_O    = 33280;          // 64*260
constexpr int OFF_Q    = 49920;          // 64*36
constexpr int OFF_K    = 52224;
constexpr int OFF_V    = 54528;
constexpr int OFF_N1   = 56832;          // 256
constexpr int OFF_N2   = 57088;          // 256
constexpr int OFF_BT   = 57344;          // 49 (padded 64)
constexpr int SMEM_FLOATS = 57408;       // 229632 bytes

__device__ __forceinline__ unsigned f2tf(float f) {
    unsigned u;
    asm("cvt.rna.tf32.f32 %0, %1;" : "=r"(u) : "f"(f));
    return u;
}
__device__ __forceinline__ unsigned fau(float f) { return __float_as_uint(f); }
__device__ __forceinline__ float uaf(unsigned u) { return __uint_as_float(u); }

__device__ __forceinline__ void mma8(float* c,
                                     unsigned a0, unsigned a1, unsigned a2, unsigned a3,
                                     unsigned b0, unsigned b1) {
    asm("mma.sync.aligned.m16n8k8.row.col.f32.tf32.tf32.f32 "
        "{%0,%1,%2,%3},{%4,%5,%6,%7},{%8,%9},{%0,%1,%2,%3};"
        : "+f"(c[0]), "+f"(c[1]), "+f"(c[2]), "+f"(c[3])
        : "r"(a0), "r"(a1), "r"(a2), "r"(a3), "r"(b0), "r"(b1));
}

__global__ void __launch_bounds__(256, 1)
winattn_kernel(const float* __restrict__ x, const float* __restrict__ cond,
               const float* __restrict__ n1w, const float* __restrict__ n2w,
               const float* __restrict__ wq, const float* __restrict__ bq,
               const float* __restrict__ wkv, const float* __restrict__ bkv,
               const float* __restrict__ wo, const float* __restrict__ bo,
               const float* __restrict__ btab, float* __restrict__ out) {
    extern __shared__ float sm[];
    const int tid = threadIdx.x;

    // stage LN weights + bias table
    sm[OFF_N1 + tid] = n1w[tid];
    sm[OFF_N2 + tid] = n2w[tid];
    if (tid < 49) sm[OFF_BT + tid] = btab[tid];

    // window group: 4 consecutive wb in one (b, hb) row -> 16 contiguous pixels per (c, i)
    const int gw0 = blockIdx.x * 4;
    const int b   = gw0 / (96 * 96);
    const int rem = gw0 % (96 * 96);
    const int hb  = rem / 96;
    const int wb0 = rem % 96;
    const int h0  = hb * 4;
    const int w0  = wb0 * 4;

    // ---- Phase 1: load (coalesced 64B segments) + transpose to [token][channel] ----
    for (int idx = tid; idx < 16384; idx += 256) {
        int p = idx & 15, i = (idx >> 4) & 3, c = idx >> 6;
        int gaddr = ((b * 256 + c) * 384 + h0 + i) * 384 + w0 + p;
        int row = ((p >> 2) << 4) + (i << 2) + (p & 3);
        sm[OFF_QIN + row * LDA + c]  = cond[gaddr];
        sm[OFF_KVIN + row * LDA + c] = x[gaddr];
    }
    __syncthreads();

    // ---- LayerNorm (bias-free), store tf32-rounded. 4 threads per token row ----
    {
        int row = tid >> 2, q = tid & 3;
        float* R1 = sm + OFF_QIN + row * LDA;
        float* R2 = sm + OFF_KVIN + row * LDA;
        float s1 = 0.f, ss1 = 0.f, s2 = 0.f, ss2 = 0.f;
        for (int c = q; c < 256; c += 4) {
            float v1 = R1[c]; s1 += v1; ss1 += v1 * v1;
            float v2 = R2[c]; s2 += v2; ss2 += v2 * v2;
        }
        s1  += __shfl_xor_sync(~0u, s1, 1);  s1  += __shfl_xor_sync(~0u, s1, 2);
        ss1 += __shfl_xor_sync(~0u, ss1, 1); ss1 += __shfl_xor_sync(~0u, ss1, 2);
        s2  += __shfl_xor_sync(~0u, s2, 1);  s2  += __shfl_xor_sync(~0u, s2, 2);
        ss2 += __shfl_xor_sync(~0u, ss2, 1); ss2 += __shfl_xor_sync(~0u, ss2, 2);
        float m1 = s1 * (1.f / 256.f), v1 = ss1 * (1.f / 256.f) - m1 * m1;
        float m2 = s2 * (1.f / 256.f), v2 = ss2 * (1.f / 256.f) - m2 * m2;
        float r1 = rsqrtf(v1 + 1e-5f), r2 = rsqrtf(v2 + 1e-5f);
        for (int c = q; c < 256; c += 4) {
            R1[c] = uaf(f2tf((R1[c] - m1) * r1 * sm[OFF_N1 + c]));
            R2[c] = uaf(f2tf((R2[c] - m2) * r2 * sm[OFF_N2 + c]));
        }
    }

    const int lane = tid & 31, warp = tid >> 5;
    const int g = lane >> 2, tg = lane & 3;

    // ---- Phase 2: per head (sequential): QKV GEMM then attention ----
    for (int h = 0; h < 8; h++) {
        __syncthreads();   // LN done / previous attention done before overwriting sQ/sK/sV
        if (warp < 4) {
            // Q strip: cols [h*32 + warp*8, +8), A = sQin (64x256)
            const int colb = h * 32 + warp * 8;
            float acc[4][4] = {};
            #pragma unroll 2
            for (int k0 = 0; k0 < 256; k0 += 8) {
                unsigned b0 = f2tf(__ldg(wq + (k0 + tg) * 256 + colb + g));
                unsigned b1 = f2tf(__ldg(wq + (k0 + tg + 4) * 256 + colb + g));
                #pragma unroll
                for (int m = 0; m < 4; m++) {
                    const float* A = sm + OFF_QIN + (m * 16 + g) * LDA + k0 + tg;
                    unsigned a0 = fau(A[0]), a2 = fau(A[4]);
                    unsigned a1 = fau(A[8 * LDA]), a3 = fau(A[8 * LDA + 4]);
                    mma8(acc[m], a0, a1, a2, a3, b0, b1);
                }
            }
            float bb0 = __ldg(bq + colb + 2 * tg), bb1 = __ldg(bq + colb + 2 * tg + 1);
            #pragma unroll
            for (int m = 0; m < 4; m++) {
                float* D = sm + OFF_Q + (m * 16 + g) * LDQ + warp * 8 + 2 * tg;
                D[0] = uaf(f2tf(acc[m][0] + bb0));
                D[1] = uaf(f2tf(acc[m][1] + bb1));
                D[8 * LDQ]     = uaf(f2tf(acc[m][2] + bb0));
                D[8 * LDQ + 1] = uaf(f2tf(acc[m][3] + bb1));
            }
        } else {
            // K and V strips share A-fragments (A = sKVin)
            const int s4 = warp - 4;
            const int ck = h * 32 + s4 * 8, cv = 256 + ck;
            float aK[4][4] = {}, aV[4][4] = {};
            #pragma unroll 2
            for (int k0 = 0; k0 < 256; k0 += 8) {
                const float* W0 = wkv + (k0 + tg) * 512;
                const float* W1 = wkv + (k0 + tg + 4) * 512;
                unsigned bk0 = f2tf(__ldg(W0 + ck + g)), bk1 = f2tf(__ldg(W1 + ck + g));
                unsigned bv0 = f2tf(__ldg(W0 + cv + g)), bv1 = f2tf(__ldg(W1 + cv + g));
                #pragma unroll
                for (int m = 0; m < 4; m++) {
                    const float* A = sm + OFF_KVIN + (m * 16 + g) * LDA + k0 + tg;
                    unsigned a0 = fau(A[0]), a2 = fau(A[4]);
                    unsigned a1 = fau(A[8 * LDA]), a3 = fau(A[8 * LDA + 4]);
                    mma8(aK[m], a0, a1, a2, a3, bk0, bk1);
                    mma8(aV[m], a0, a1, a2, a3, bv0, bv1);
                }
            }
            float bk0 = __ldg(bkv + ck + 2 * tg), bk1 = __ldg(bkv + ck + 2 * tg + 1);
            float bv0 = __ldg(bkv + cv + 2 * tg), bv1 = __ldg(bkv + cv + 2 * tg + 1);
            #pragma unroll
            for (int m = 0; m < 4; m++) {
                float* DK = sm + OFF_K + (m * 16 + g) * LDQ + s4 * 8 + 2 * tg;
                float* DV = sm + OFF_V + (m * 16 + g) * LDQ + s4 * 8 + 2 * tg;
                DK[0] = uaf(f2tf(aK[m][0] + bk0)); DK[1] = uaf(f2tf(aK[m][1] + bk1));
                DK[8 * LDQ] = uaf(f2tf(aK[m][2] + bk0)); DK[8 * LDQ + 1] = uaf(f2tf(aK[m][3] + bk1));
                DV[0] = uaf(f2tf(aV[m][0] + bv0)); DV[1] = uaf(f2tf(aV[m][1] + bv1));
                DV[8 * LDQ] = uaf(f2tf(aV[m][2] + bv0)); DV[8 * LDQ + 1] = uaf(f2tf(aV[m][3] + bv1));
            }
        }
        __syncthreads();

        if (warp < 4) {
            // attention for window 'warp' (rows rb..rb+15), this head
            const int rb = warp * 16;
            float sc[2][4] = {};
            #pragma unroll
            for (int k0 = 0; k0 < 32; k0 += 8) {
                const float* A = sm + OFF_Q + (rb + g) * LDQ + k0 + tg;
                unsigned a0 = fau(A[0]), a2 = fau(A[4]);
                unsigned a1 = fau(A[8 * LDQ]), a3 = fau(A[8 * LDQ + 4]);
                #pragma unroll
                for (int nt = 0; nt < 2; nt++) {
                    const float* B = sm + OFF_K + (rb + nt * 8 + g) * LDQ + k0 + tg;
                    mma8(sc[nt], a0, a1, a2, a3, fau(B[0]), fau(B[4]));
                }
            }
            // scale + relative-position bias
            const float SCL = 0.17677669529663687f;  // 1/sqrt(32)
            const float* BT = sm + OFF_BT;
            #pragma unroll
            for (int nt = 0; nt < 2; nt++)
                #pragma unroll
                for (int e = 0; e < 4; e++) {
                    int r  = g + ((e >> 1) << 3);
                    int cc = nt * 8 + 2 * tg + (e & 1);
                    sc[nt][e] = sc[nt][e] * SCL +
                                BT[((r >> 2) - (cc >> 2) + 3) * 7 + ((r & 3) - (cc & 3) + 3)];
                }
            // softmax over 16 keys: row g (regs e=0,1), row g+8 (regs e=2,3); 4 lanes/row
            #pragma unroll
            for (int half = 0; half < 2; half++) {
                int e0 = half * 2;
                float mx = fmaxf(fmaxf(sc[0][e0], sc[0][e0 + 1]),
                                 fmaxf(sc[1][e0], sc[1][e0 + 1]));
                mx = fmaxf(mx, __shfl_xor_sync(~0u, mx, 1));
                mx = fmaxf(mx, __shfl_xor_sync(~0u, mx, 2));
                float t00 = __expf(sc[0][e0] - mx),     t01 = __expf(sc[0][e0 + 1] - mx);
                float t10 = __expf(sc[1][e0] - mx),     t11 = __expf(sc[1][e0 + 1] - mx);
                float sum = t00 + t01 + t10 + t11;
                sum += __shfl_xor_sync(~0u, sum, 1);
                sum += __shfl_xor_sync(~0u, sum, 2);
                float inv = 1.0f / sum;
                sc[0][e0] = t00 * inv; sc[0][e0 + 1] = t01 * inv;
                sc[1][e0] = t10 * inv; sc[1][e0 + 1] = t11 * inv;
            }
            // store P (tf32) into sQ rows of this window (warp-private rows)
            #pragma unroll
            for (int nt = 0; nt < 2; nt++) {
                float* D = sm + OFF_Q + (rb + g) * LDQ + nt * 8 + 2 * tg;
                D[0] = uaf(f2tf(sc[nt][0])); D[1] = uaf(f2tf(sc[nt][1]));
                D[8 * LDQ] = uaf(f2tf(sc[nt][2])); D[8 * LDQ + 1] = uaf(f2tf(sc[nt][3]));
            }
            __syncwarp();
            // O = P @ V  (16x32)
            float ov[4][4] = {};
            #pragma unroll
            for (int k0 = 0; k0 < 16; k0 += 8) {
                const float* A = sm + OFF_Q + (rb + g) * LDQ + k0 + tg;
                unsigned a0 = fau(A[0]), a2 = fau(A[4]);
                unsigned a1 = fau(A[8 * LDQ]), a3 = fau(A[8 * LDQ + 4]);
                #pragma unroll
                for (int nt = 0; nt < 4; nt++) {
                    const float* B = sm + OFF_V + (rb + k0 + tg) * LDQ + nt * 8 + g;
                    mma8(ov[nt], a0, a1, a2, a3, fau(B[0]), fau(B[4 * LDQ]));
                }
            }
            // write O slice (head-disjoint columns), tf32-rounded (A-operand of phase 3)
            #pragma unroll
            for (int nt = 0; nt < 4; nt++) {
                float* D = sm + OFF_O + (rb + g) * LDA + h * 32 + nt * 8 + 2 * tg;
                D[0] = uaf(f2tf(ov[nt][0])); D[1] = uaf(f2tf(ov[nt][1]));
                D[8 * LDA] = uaf(f2tf(ov[nt][2])); D[8 * LDA + 1] = uaf(f2tf(ov[nt][3]));
            }
        }
    }
    __syncthreads();

    // ---- Phase 3: Y = O @ wo + bo ; each warp owns 4 n-strips (cols warp*8 + j*64) ----
    {
        float acc[4][4][4] = {};
        for (int k0 = 0; k0 < 256; k0 += 8) {
            unsigned a[4][4];
            #pragma unroll
            for (int m = 0; m < 4; m++) {
                const float* A = sm + OFF_O + (m * 16 + g) * LDA + k0 + tg;
                a[m][0] = fau(A[0]); a[m][2] = fau(A[4]);
                a[m][1] = fau(A[8 * LDA]); a[m][3] = fau(A[8 * LDA + 4]);
            }
            #pragma unroll
            for (int j = 0; j < 4; j++) {
                int col = warp * 8 + j * 64 + g;
                unsigned b0 = f2tf(__ldg(wo + (k0 + tg) * 256 + col));
                unsigned b1 = f2tf(__ldg(wo + (k0 + tg + 4) * 256 + col));
                #pragma unroll
                for (int m = 0; m < 4; m++)
                    mma8(acc[j][m], a[m][0], a[m][1], a[m][2], a[m][3], b0, b1);
            }
        }
        // stage Y into sQin (dead) for coalesced write-out
        #pragma unroll
        for (int j = 0; j < 4; j++) {
            int c0 = warp * 8 + j * 64 + 2 * tg;
            float bb0 = __ldg(bo + c0), bb1 = __ldg(bo + c0 + 1);
            #pragma unroll
            for (int m = 0; m < 4; m++) {
                float* D = sm + OFF_QIN + (m * 16 + g) * LDA + c0;
                D[0] = acc[j][m][0] + bb0;
                D[1] = acc[j][m][1] + bb1;
                D[8 * LDA]     = acc[j][m][2] + bb0;
                D[8 * LDA + 1] = acc[j][m][3] + bb1;
            }
        }
    }
    __syncthreads();

    // ---- Phase 4: residual add + coalesced scatter back to (B,C,H,W) ----
    for (int idx = tid; idx < 16384; idx += 256) {
        int p = idx & 15, i = (idx >> 4) & 3, c = idx >> 6;
        int gaddr = ((b * 256 + c) * 384 + h0 + i) * 384 + w0 + p;
        int row = ((p >> 2) << 4) + (i << 2) + (p & 3);
        out[gaddr] = x[gaddr] + sm[OFF_QIN + row * LDA + c];
    }
}

extern "C" void kernel_launch(void* const* d_in, const int* in_sizes, int n_in,
                              void* d_out, int out_size) {
    const float* x    = (const float*)d_in[0];
    const float* cond = (const float*)d_in[1];
    const float* n1w  = (const float*)d_in[2];
    const float* n2w  = (const float*)d_in[3];
    const float* wq   = (const float*)d_in[4];
    const float* bq   = (const float*)d_in[5];
    const float* wkv  = (const float*)d_in[6];
    const float* bkv  = (const float*)d_in[7];
    const float* wo   = (const float*)d_in[8];
    const float* bo   = (const float*)d_in[9];
    const float* btab = (const float*)d_in[10];
    float* out = (float*)d_out;

    size_t shmem = SMEM_FLOATS * sizeof(float);
    cudaFuncSetAttribute(winattn_kernel, cudaFuncAttributeMaxDynamicSharedMemorySize, (int)shmem);

    // 18432 windows / 4 per CTA
    winattn_kernel<<<4608, 256, shmem>>>(x, cond, n1w, n2w, wq, bq, wkv, bkv,
                                         wo, bo, btab, out);
}

// round 3
// speedup vs baseline: 1.1485x; 1.1485x over previous
#include <cuda_runtime.h>
#include <cuda_bf16.h>

// Fused Swin-window cross-attention, tf32 mma.sync, round 2 (resubmit — broker timeout).
// C=256, H=W=384, WS=4, 8 heads, hd=32. CTA = 4 windows (64 tokens), 512 threads.
// Heads processed in 4 groups of 2; Y = O @ wo accumulated in registers per group.

#define LDA 260   // stride for 64x256 input/staging buffers
#define LDB 196   // stride for the 64x192 group QKV buffer (Q|K|V, 64 cols each)

constexpr int OFF_QIN  = 0;              // 64*260
constexpr int OFF_KVIN = 16640;          // 64*260
constexpr int OFF_GB   = 33280;          // 64*196 = 12544
constexpr int OFF_N1   = 45824;          // 256
constexpr int OFF_N2   = 46080;          // 256
constexpr int OFF_BT   = 46336;          // 49 pad 64
constexpr int SMEM_FLOATS = 46400;       // 185600 bytes

__device__ __forceinline__ unsigned f2tf(float f) {
    unsigned u;
    asm("cvt.rna.tf32.f32 %0, %1;" : "=r"(u) : "f"(f));
    return u;
}
__device__ __forceinline__ unsigned fau(float f) { return __float_as_uint(f); }
__device__ __forceinline__ float uaf(unsigned u) { return __uint_as_float(u); }

__device__ __forceinline__ void mma8(float* c,
                                     unsigned a0, unsigned a1, unsigned a2, unsigned a3,
                                     unsigned b0, unsigned b1) {
    asm("mma.sync.aligned.m16n8k8.row.col.f32.tf32.tf32.f32 "
        "{%0,%1,%2,%3},{%4,%5,%6,%7},{%8,%9},{%0,%1,%2,%3};"
        : "+f"(c[0]), "+f"(c[1]), "+f"(c[2]), "+f"(c[3])
        : "r"(a0), "r"(a1), "r"(a2), "r"(a3), "r"(b0), "r"(b1));
}

__global__ void __launch_bounds__(512, 1)
winattn_kernel(const float* __restrict__ x, const float* __restrict__ cond,
               const float* __restrict__ n1w, const float* __restrict__ n2w,
               const float* __restrict__ wq, const float* __restrict__ bq,
               const float* __restrict__ wkv, const float* __restrict__ bkv,
               const float* __restrict__ wo, const float* __restrict__ bo,
               const float* __restrict__ btab, float* __restrict__ out) {
    extern __shared__ float sm[];
    const int tid = threadIdx.x;

    if (tid < 256) { sm[OFF_N1 + tid] = n1w[tid]; sm[OFF_N2 + tid] = n2w[tid]; }
    if (tid < 49)  sm[OFF_BT + tid] = btab[tid];

    // 4 consecutive windows in one (b, hb) row -> 16 contiguous pixels per (c, i)
    const int gw0 = blockIdx.x * 4;
    const int b   = gw0 / (96 * 96);
    const int rem = gw0 % (96 * 96);
    const int hb  = rem / 96;
    const int wb0 = rem % 96;
    const int h0  = hb * 4;
    const int w0  = wb0 * 4;

    // ---- Phase 1: load + transpose to [token][channel] ----
    for (int idx = tid; idx < 16384; idx += 512) {
        int p = idx & 15, i = (idx >> 4) & 3, c = idx >> 6;
        int gaddr = ((b * 256 + c) * 384 + h0 + i) * 384 + w0 + p;
        int row = ((p >> 2) << 4) + (i << 2) + (p & 3);
        sm[OFF_QIN + row * LDA + c]  = cond[gaddr];
        sm[OFF_KVIN + row * LDA + c] = x[gaddr];
    }
    __syncthreads();

    // ---- LayerNorm (bias-free), vectorized; 8 threads per token row ----
    {
        int row = tid >> 3, q = tid & 7;
        float* R1 = sm + OFF_QIN + row * LDA;
        float* R2 = sm + OFF_KVIN + row * LDA;
        float s1 = 0.f, ss1 = 0.f, s2 = 0.f, ss2 = 0.f;
        #pragma unroll
        for (int j = 0; j < 8; j++) {
            float4 v1 = *(const float4*)(R1 + q * 4 + j * 32);
            float4 v2 = *(const float4*)(R2 + q * 4 + j * 32);
            s1 += v1.x + v1.y + v1.z + v1.w;
            ss1 += v1.x * v1.x + v1.y * v1.y + v1.z * v1.z + v1.w * v1.w;
            s2 += v2.x + v2.y + v2.z + v2.w;
            ss2 += v2.x * v2.x + v2.y * v2.y + v2.z * v2.z + v2.w * v2.w;
        }
        #pragma unroll
        for (int d = 1; d < 8; d <<= 1) {
            s1  += __shfl_xor_sync(~0u, s1, d);  ss1 += __shfl_xor_sync(~0u, ss1, d);
            s2  += __shfl_xor_sync(~0u, s2, d);  ss2 += __shfl_xor_sync(~0u, ss2, d);
        }
        float m1 = s1 * (1.f / 256.f), v1 = ss1 * (1.f / 256.f) - m1 * m1;
        float m2 = s2 * (1.f / 256.f), v2 = ss2 * (1.f / 256.f) - m2 * m2;
        float r1 = rsqrtf(v1 + 1e-5f), r2 = rsqrtf(v2 + 1e-5f);
        #pragma unroll
        for (int j = 0; j < 8; j++) {
            int c = q * 4 + j * 32;
            float4 a = *(const float4*)(R1 + c);
            float4 bvec = *(const float4*)(R2 + c);
            float4 g1 = *(const float4*)(sm + OFF_N1 + c);
            float4 g2 = *(const float4*)(sm + OFF_N2 + c);
            a.x = uaf(f2tf((a.x - m1) * r1 * g1.x));
            a.y = uaf(f2tf((a.y - m1) * r1 * g1.y));
            a.z = uaf(f2tf((a.z - m1) * r1 * g1.z));
            a.w = uaf(f2tf((a.w - m1) * r1 * g1.w));
            bvec.x = uaf(f2tf((bvec.x - m2) * r2 * g2.x));
            bvec.y = uaf(f2tf((bvec.y - m2) * r2 * g2.y));
            bvec.z = uaf(f2tf((bvec.z - m2) * r2 * g2.z));
            bvec.w = uaf(f2tf((bvec.w - m2) * r2 * g2.w));
            *(float4*)(R1 + c) = a;
            *(float4*)(R2 + c) = bvec;
        }
    }
    __syncthreads();

    const int lane = tid & 31, warp = tid >> 5;
    const int gl = lane >> 2, tg = lane & 3;

    float yacc[4][2][4] = {};   // Y = O @ wo, accumulated across head groups

    for (int hg = 0; hg < 8; hg += 2) {
        const int chead = hg * 32;      // channel base of this 2-head group

        // ---- QKV GEMM for group: 64x256 @ 256x192 -> GB (Q|K|V) ----
        if (warp < 12) {
            const int mh = warp / 6, slot = warp % 6;
            const float* Ain = sm + (slot < 2 ? OFF_QIN : OFF_KVIN) + (mh * 32 + gl) * LDA + tg;
            const float* Wb; int ldb, cb; const float* bias; int dcb;
            if (slot < 2)      { Wb = wq;  ldb = 256; cb = chead + slot * 32;        bias = bq;  dcb = slot * 32; }
            else if (slot < 4) { Wb = wkv; ldb = 512; cb = chead + (slot - 2) * 32;  bias = bkv; dcb = 64 + (slot - 2) * 32; }
            else               { Wb = wkv; ldb = 512; cb = 256 + chead + (slot - 4) * 32; bias = bkv; dcb = 128 + (slot - 4) * 32; }

            float acc[4][2][4] = {};
            for (int k0 = 0; k0 < 256; k0 += 8) {
                unsigned bf0[4], bf1[4];
                const float* W0 = Wb + (k0 + tg) * ldb + cb + gl;
                const float* W1 = W0 + 4 * ldb;
                #pragma unroll
                for (int j = 0; j < 4; j++) {
                    bf0[j] = f2tf(__ldg(W0 + j * 8));
                    bf1[j] = f2tf(__ldg(W1 + j * 8));
                }
                #pragma unroll
                for (int m = 0; m < 2; m++) {
                    const float* A = Ain + m * 16 * LDA + k0;
                    unsigned a0 = fau(A[0]), a2 = fau(A[4]);
                    unsigned a1 = fau(A[8 * LDA]), a3 = fau(A[8 * LDA + 4]);
                    #pragma unroll
                    for (int j = 0; j < 4; j++)
                        mma8(acc[j][m], a0, a1, a2, a3, bf0[j], bf1[j]);
                }
            }
            #pragma unroll
            for (int j = 0; j < 4; j++) {
                float bb0 = __ldg(bias + cb + j * 8 + 2 * tg);
                float bb1 = __ldg(bias + cb + j * 8 + 2 * tg + 1);
                #pragma unroll
                for (int m = 0; m < 2; m++) {
                    float* D = sm + OFF_GB + (mh * 32 + m * 16 + gl) * LDB + dcb + j * 8 + 2 * tg;
                    D[0] = uaf(f2tf(acc[j][m][0] + bb0));
                    D[1] = uaf(f2tf(acc[j][m][1] + bb1));
                    D[8 * LDB]     = uaf(f2tf(acc[j][m][2] + bb0));
                    D[8 * LDB + 1] = uaf(f2tf(acc[j][m][3] + bb1));
                }
            }
        }
        __syncthreads();

        // ---- Attention: 8 units (2 heads x 4 windows), one per warp ----
        if (warp < 8) {
            const int hh = warp >> 2, wi = warp & 3, rb = wi * 16;
            float* sQ = sm + OFF_GB + hh * 32;
            float* sK = sm + OFF_GB + 64 + hh * 32;
            float* sV = sm + OFF_GB + 128 + hh * 32;

            float sc[2][4] = {};
            #pragma unroll
            for (int k0 = 0; k0 < 32; k0 += 8) {
                const float* A = sQ + (rb + gl) * LDB + k0 + tg;
                unsigned a0 = fau(A[0]), a2 = fau(A[4]);
                unsigned a1 = fau(A[8 * LDB]), a3 = fau(A[8 * LDB + 4]);
                #pragma unroll
                for (int nt = 0; nt < 2; nt++) {
                    const float* B = sK + (rb + nt * 8 + gl) * LDB + k0 + tg;
                    mma8(sc[nt], a0, a1, a2, a3, fau(B[0]), fau(B[4]));
                }
            }
            const float SCL = 0.17677669529663687f;  // 1/sqrt(32)
            const float* BT = sm + OFF_BT;
            #pragma unroll
            for (int nt = 0; nt < 2; nt++)
                #pragma unroll
                for (int e = 0; e < 4; e++) {
                    int r  = gl + ((e >> 1) << 3);
                    int cc = nt * 8 + 2 * tg + (e & 1);
                    sc[nt][e] = sc[nt][e] * SCL +
                                BT[((r >> 2) - (cc >> 2) + 3) * 7 + ((r & 3) - (cc & 3) + 3)];
                }
            #pragma unroll
            for (int half = 0; half < 2; half++) {
                int e0 = half * 2;
                float mx = fmaxf(fmaxf(sc[0][e0], sc[0][e0 + 1]),
                                 fmaxf(sc[1][e0], sc[1][e0 + 1]));
                mx = fmaxf(mx, __shfl_xor_sync(~0u, mx, 1));
                mx = fmaxf(mx, __shfl_xor_sync(~0u, mx, 2));
                float t00 = __expf(sc[0][e0] - mx), t01 = __expf(sc[0][e0 + 1] - mx);
                float t10 = __expf(sc[1][e0] - mx), t11 = __expf(sc[1][e0 + 1] - mx);
                float sum = t00 + t01 + t10 + t11;
                sum += __shfl_xor_sync(~0u, sum, 1);
                sum += __shfl_xor_sync(~0u, sum, 2);
                float inv = 1.0f / sum;
                sc[0][e0] = t00 * inv; sc[0][e0 + 1] = t01 * inv;
                sc[1][e0] = t10 * inv; sc[1][e0 + 1] = t11 * inv;
            }
            // P -> first 16 cols of own Q slice (dead)
            #pragma unroll
            for (int nt = 0; nt < 2; nt++) {
                float* D = sQ + (rb + gl) * LDB + nt * 8 + 2 * tg;
                D[0] = uaf(f2tf(sc[nt][0])); D[1] = uaf(f2tf(sc[nt][1]));
                D[8 * LDB] = uaf(f2tf(sc[nt][2])); D[8 * LDB + 1] = uaf(f2tf(sc[nt][3]));
            }
            __syncwarp();
            // O = P @ V (16x32)
            float ov[4][4] = {};
            #pragma unroll
            for (int k0 = 0; k0 < 16; k0 += 8) {
                const float* A = sQ + (rb + gl) * LDB + k0 + tg;
                unsigned a0 = fau(A[0]), a2 = fau(A[4]);
                unsigned a1 = fau(A[8 * LDB]), a3 = fau(A[8 * LDB + 4]);
                #pragma unroll
                for (int nt = 0; nt < 4; nt++) {
                    const float* B = sV + (rb + k0 + tg) * LDB + nt * 8 + gl;
                    mma8(ov[nt], a0, a1, a2, a3, fau(B[0]), fau(B[4 * LDB]));
                }
            }
            // O overwrites this unit's own K slice (disjoint per warp)
            #pragma unroll
            for (int nt = 0; nt < 4; nt++) {
                float* D = sK + (rb + gl) * LDB + nt * 8 + 2 * tg;
                D[0] = uaf(f2tf(ov[nt][0])); D[1] = uaf(f2tf(ov[nt][1]));
                D[8 * LDB] = uaf(f2tf(ov[nt][2])); D[8 * LDB + 1] = uaf(f2tf(ov[nt][3]));
            }
        }
        __syncthreads();

        // ---- Partial O-proj: Y += O(64x64) @ wo[chead:chead+64, :] ; all 16 warps ----
        {
            const int mh = warp >> 3, wl = warp & 7;
            const float* Abase = sm + OFF_GB + 64 + (mh * 32 + gl) * LDB + tg;
            #pragma unroll
            for (int k0 = 0; k0 < 64; k0 += 8) {
                unsigned bf0[4], bf1[4];
                const float* W0 = wo + (chead + k0 + tg) * 256 + wl * 8 + gl;
                const float* W1 = W0 + 4 * 256;
                #pragma unroll
                for (int j = 0; j < 4; j++) {
                    bf0[j] = f2tf(__ldg(W0 + j * 64));
                    bf1[j] = f2tf(__ldg(W1 + j * 64));
                }
                #pragma unroll
                for (int m = 0; m < 2; m++) {
                    const float* A = Abase + m * 16 * LDB + k0;
                    unsigned a0 = fau(A[0]), a2 = fau(A[4]);
                    unsigned a1 = fau(A[8 * LDB]), a3 = fau(A[8 * LDB + 4]);
                    #pragma unroll
                    for (int j = 0; j < 4; j++)
                        mma8(yacc[j][m], a0, a1, a2, a3, bf0[j], bf1[j]);
                }
            }
        }
        __syncthreads();   // protect GB before next group's QKV overwrite
    }

    // ---- Stage Y + bias into sQIN (dead) for coalesced writeout ----
    {
        const int mh = warp >> 3, wl = warp & 7;
        #pragma unroll
        for (int j = 0; j < 4; j++) {
            int c0 = wl * 8 + j * 64 + 2 * tg;
            float bb0 = __ldg(bo + c0), bb1 = __ldg(bo + c0 + 1);
            #pragma unroll
            for (int m = 0; m < 2; m++) {
                float* D = sm + OFF_QIN + (mh * 32 + m * 16 + gl) * LDA + c0;
                D[0] = yacc[j][m][0] + bb0;
                D[1] = yacc[j][m][1] + bb1;
                D[8 * LDA]     = yacc[j][m][2] + bb0;
                D[8 * LDA + 1] = yacc[j][m][3] + bb1;
            }
        }
    }
    __syncthreads();

    // ---- Residual add + coalesced scatter to (B,C,H,W) ----
    for (int idx = tid; idx < 16384; idx += 512) {
        int p = idx & 15, i = (idx >> 4) & 3, c = idx >> 6;
        int gaddr = ((b * 256 + c) * 384 + h0 + i) * 384 + w0 + p;
        int row = ((p >> 2) << 4) + (i << 2) + (p & 3);
        out[gaddr] = x[gaddr] + sm[OFF_QIN + row * LDA + c];
    }
}

extern "C" void kernel_launch(void* const* d_in, const int* in_sizes, int n_in,
                              void* d_out, int out_size) {
    const float* x    = (const float*)d_in[0];
    const float* cond = (const float*)d_in[1];
    const float* n1w  = (const float*)d_in[2];
    const float* n2w  = (const float*)d_in[3];
    const float* wq   = (const float*)d_in[4];
    const float* bq   = (const float*)d_in[5];
    const float* wkv  = (const float*)d_in[6];
    const float* bkv  = (const float*)d_in[7];
    const float* wo   = (const float*)d_in[8];
    const float* bo   = (const float*)d_in[9];
    const float* btab = (const float*)d_in[10];
    float* out = (float*)d_out;

    size_t shmem = SMEM_FLOATS * sizeof(float);
    cudaFuncSetAttribute(winattn_kernel, cudaFuncAttributeMaxDynamicSharedMemorySize, (int)shmem);

    winattn_kernel<<<4608, 512, shmem>>>(x, cond, n1w, n2w, wq, bq, wkv, bkv,
                                         wo, bo, btab, out);
}